// round 7
// baseline (speedup 1.0000x reference)
#include <cuda_runtime.h>
#include <cuda_fp16.h>
#include <cuda_bf16.h>
#include <stdint.h>

#define NN 100000
#define NE 800000
#define C  100
#define OC 50

#define TM 128
#define NTILES ((NN + TM - 1) / TM)
#define GEMM_GRID 148
#define GEMM_THREADS 256

// word stride per row (30 words data + pad -> 60 keeps frag LDS conflict-free)
#define WS 60

// GEMM1 smem layout (words): A hi/lo bf16 + B hi/lo bf16
#define G1_AHI 0
#define G1_ALO (128 * WS)
#define G1_BHI (2 * 128 * WS)
#define G1_BLO (G1_BHI + 104 * WS)
#define G1_WORDS (G1_BLO + 104 * WS)       // 27840 words = 111360 B

// GEMM2 smem layout (words): A fp16 (single) + B hi/lo fp16
#define G2_A   0
#define G2_BHI (128 * WS)
#define G2_BLO (G2_BHI + 104 * WS)
#define G2_WORDS (G2_BLO + 104 * WS)       // 20160 words = 80640 B

// ---------------- device globals (scratch; zero-initialized at load) ----------------
__device__ __align__(16) float d_dis[NN];
__device__ __align__(16) __half d_G16[NN * C];
__device__ __align__(16) __half d_H16[NN * C];
__device__ int d_cnt[NN];      // zeroed at end of every run (gather mode 1)
__device__ int d_start[NN];    // after k_fill: END pointers
__device__ int d_csr[NE];
__device__ int d_total;        // zeroed at end of every run

// ---------------- mma helpers (baseline PTX, sm_80+) ----------------
__device__ __forceinline__ void mma_bf16(float* d, const uint32_t* a, const uint32_t* b) {
    asm volatile(
        "mma.sync.aligned.m16n8k16.row.col.f32.bf16.bf16.f32 "
        "{%0,%1,%2,%3}, {%4,%5,%6,%7}, {%8,%9}, {%0,%1,%2,%3};"
        : "+f"(d[0]), "+f"(d[1]), "+f"(d[2]), "+f"(d[3])
        : "r"(a[0]), "r"(a[1]), "r"(a[2]), "r"(a[3]), "r"(b[0]), "r"(b[1]));
}
__device__ __forceinline__ void mma_f16(float* d, const uint32_t* a, const uint32_t* b) {
    asm volatile(
        "mma.sync.aligned.m16n8k16.row.col.f32.f16.f16.f32 "
        "{%0,%1,%2,%3}, {%4,%5,%6,%7}, {%8,%9}, {%0,%1,%2,%3};"
        : "+f"(d[0]), "+f"(d[1]), "+f"(d[2]), "+f"(d[3])
        : "r"(a[0]), "r"(a[1]), "r"(a[2]), "r"(a[3]), "r"(b[0]), "r"(b[1]));
}
__device__ __forceinline__ uint32_t pack_bf2(__nv_bfloat16 a, __nv_bfloat16 b) {
    __nv_bfloat162 v = __halves2bfloat162(a, b);
    return *reinterpret_cast<uint32_t*>(&v);
}

// ---------------- CSR build (3 launches) ----------------
__global__ void k_deg(const int* __restrict__ dst) {
    int e = blockIdx.x * blockDim.x + threadIdx.x;
    if (e < NE) atomicAdd(&d_cnt[dst[e]], 1);    // d_cnt pre-zeroed (load / prior run)
}

// block scan + single global atomic to allocate contiguous CSR ranges; also dis.
__global__ void k_alloc() {
    __shared__ int sh[1024];
    __shared__ int sbase;
    int i = blockIdx.x * 1024 + threadIdx.x;
    int v = (i < NN) ? d_cnt[i] : 0;
    sh[threadIdx.x] = v;
    __syncthreads();
    for (int off = 1; off < 1024; off <<= 1) {
        int t = (threadIdx.x >= off) ? sh[threadIdx.x - off] : 0;
        __syncthreads();
        sh[threadIdx.x] += t;
        __syncthreads();
    }
    if (threadIdx.x == 1023) sbase = atomicAdd(&d_total, sh[1023]);
    __syncthreads();
    if (i < NN) {
        d_start[i] = sbase + sh[threadIdx.x] - v;   // exclusive start
        d_dis[i] = rsqrtf((float)v + 1.0f);
    }
}

__global__ void k_fill(const int* __restrict__ src, const int* __restrict__ dst) {
    int e = blockIdx.x * blockDim.x + threadIdx.x;
    if (e >= NE) return;
    int d = dst[e];
    int p = atomicAdd(&d_start[d], 1);   // start[] becomes END pointers
    d_csr[p] = src[e];
}

// ---------------- GEMM1: G16 = dis[row] * (x @ W1), bf16 split-3 ----------------
__global__ void __launch_bounds__(GEMM_THREADS, 1)
k_gemm1(const float* __restrict__ Ain, const float* __restrict__ W0) {
    extern __shared__ uint32_t sm[];
    const int tid = threadIdx.x, wid = tid >> 5, lane = tid & 31;
    const int g = lane >> 2, tg = lane & 3;

    for (int i = tid; i < G1_WORDS; i += GEMM_THREADS) sm[i] = 0;
    __syncthreads();

    for (int idx = tid; idx < C * C; idx += GEMM_THREADS) {
        int k = idx / C, n = idx % C;
        float w = W0[idx];
        __nv_bfloat16 hi = __float2bfloat16(w);
        __nv_bfloat16 lo = __float2bfloat16(w - __bfloat162float(hi));
        ((__nv_bfloat16*)(sm + G1_BHI))[(n * WS + (k >> 1)) * 2 + (k & 1)] = hi;
        ((__nv_bfloat16*)(sm + G1_BLO))[(n * WS + (k >> 1)) * 2 + (k & 1)] = lo;
    }
    __syncthreads();

    const int r0 = wid * 16;

    for (int t = blockIdx.x; t < NTILES; t += gridDim.x) {
        const int i0 = t * TM;
        const int rowlim = NN - i0;

        for (int q = tid; q < TM * 25; q += GEMM_THREADS) {
            int r = q / 25, c4 = (q % 25) * 4;
            float4 v = (r < rowlim) ? *(const float4*)&Ain[(size_t)(i0 + r) * C + c4]
                                    : make_float4(0.f, 0.f, 0.f, 0.f);
            __nv_bfloat16 hx = __float2bfloat16(v.x), hy = __float2bfloat16(v.y);
            __nv_bfloat16 hz = __float2bfloat16(v.z), hw = __float2bfloat16(v.w);
            __nv_bfloat16 lx = __float2bfloat16(v.x - __bfloat162float(hx));
            __nv_bfloat16 ly = __float2bfloat16(v.y - __bfloat162float(hy));
            __nv_bfloat16 lz = __float2bfloat16(v.z - __bfloat162float(hz));
            __nv_bfloat16 lw = __float2bfloat16(v.w - __bfloat162float(hw));
            uint32_t wbase = r * WS + (c4 >> 1);
            *(uint2*)(sm + G1_AHI + wbase) = make_uint2(pack_bf2(hx, hy), pack_bf2(hz, hw));
            *(uint2*)(sm + G1_ALO + wbase) = make_uint2(pack_bf2(lx, ly), pack_bf2(lz, lw));
        }
        __syncthreads();

        float acc[13][4];
        #pragma unroll
        for (int nt = 0; nt < 13; nt++)
            #pragma unroll
            for (int q = 0; q < 4; q++) acc[nt][q] = 0.f;

        #pragma unroll
        for (int kt = 0; kt < 7; kt++) {
            const int kw = kt * 8;
            uint32_t ah[4], al[4];
            ah[0] = sm[G1_AHI + (r0 + g) * WS + kw + tg];
            ah[1] = sm[G1_AHI + (r0 + g + 8) * WS + kw + tg];
            ah[2] = sm[G1_AHI + (r0 + g) * WS + kw + 4 + tg];
            ah[3] = sm[G1_AHI + (r0 + g + 8) * WS + kw + 4 + tg];
            al[0] = sm[G1_ALO + (r0 + g) * WS + kw + tg];
            al[1] = sm[G1_ALO + (r0 + g + 8) * WS + kw + tg];
            al[2] = sm[G1_ALO + (r0 + g) * WS + kw + 4 + tg];
            al[3] = sm[G1_ALO + (r0 + g + 8) * WS + kw + 4 + tg];
            #pragma unroll
            for (int nt = 0; nt < 13; nt++) {
                const int n0 = nt * 8;
                uint32_t bh[2], bl[2];
                bh[0] = sm[G1_BHI + (n0 + g) * WS + kw + tg];
                bh[1] = sm[G1_BHI + (n0 + g) * WS + kw + 4 + tg];
                bl[0] = sm[G1_BLO + (n0 + g) * WS + kw + tg];
                bl[1] = sm[G1_BLO + (n0 + g) * WS + kw + 4 + tg];
                mma_bf16(acc[nt], ah, bh);
                mma_bf16(acc[nt], al, bh);
                mma_bf16(acc[nt], ah, bl);
            }
        }

        const int row1 = i0 + r0 + g, row2 = row1 + 8;
        const float s1 = (row1 < NN) ? d_dis[row1] : 0.f;
        const float s2 = (row2 < NN) ? d_dis[row2] : 0.f;
        #pragma unroll
        for (int nt = 0; nt < 13; nt++) {
            const int c = nt * 8 + 2 * tg;
            if (c < C) {
                if (row1 < NN) {
                    __half2 h = __floats2half2_rn(s1 * acc[nt][0], s1 * acc[nt][1]);
                    *(__half2*)&d_G16[(size_t)row1 * C + c] = h;
                }
                if (row2 < NN) {
                    __half2 h = __floats2half2_rn(s2 * acc[nt][2], s2 * acc[nt][3]);
                    *(__half2*)&d_G16[(size_t)row2 * C + c] = h;
                }
            }
        }
        __syncthreads();
    }
}

// ---------------- GEMM2: G16 = dis[row]*(H16 @ [Wmu|Wls]), fp16 2-pass ----------------
// A = H16 exact in fp16. B = Whi + (Wlo * 2048) * 2^-11, separate accumulator.
__global__ void __launch_bounds__(GEMM_THREADS, 1)
k_gemm2(const float* __restrict__ Wa, const float* __restrict__ Wb) {
    extern __shared__ uint32_t sm[];
    const int tid = threadIdx.x, wid = tid >> 5, lane = tid & 31;
    const int g = lane >> 2, tg = lane & 3;

    for (int i = tid; i < G2_WORDS; i += GEMM_THREADS) sm[i] = 0;
    __syncthreads();

    for (int idx = tid; idx < C * C; idx += GEMM_THREADS) {
        int k = idx / C, n = idx % C;
        float w = (n < OC) ? Wa[k * OC + n] : Wb[k * OC + (n - OC)];
        __half hi = __float2half_rn(w);
        __half lo = __float2half_rn((w - __half2float(hi)) * 2048.0f);
        ((__half*)(sm + G2_BHI))[(n * WS + (k >> 1)) * 2 + (k & 1)] = hi;
        ((__half*)(sm + G2_BLO))[(n * WS + (k >> 1)) * 2 + (k & 1)] = lo;
    }
    __syncthreads();

    const int r0 = wid * 16;

    for (int t = blockIdx.x; t < NTILES; t += gridDim.x) {
        const int i0 = t * TM;
        const int rowlim = NN - i0;

        // stage A: raw fp16 copy, no conversion
        for (int q = tid; q < TM * 25; q += GEMM_THREADS) {
            int r = q / 25, c4 = (q % 25) * 4;
            uint2 v = (r < rowlim) ? *(const uint2*)&d_H16[(size_t)(i0 + r) * C + c4]
                                   : make_uint2(0u, 0u);
            *(uint2*)(sm + G2_A + r * WS + (c4 >> 1)) = v;
        }
        __syncthreads();

        float acc[13][4], acc2[13][4];
        #pragma unroll
        for (int nt = 0; nt < 13; nt++)
            #pragma unroll
            for (int q = 0; q < 4; q++) { acc[nt][q] = 0.f; acc2[nt][q] = 0.f; }

        #pragma unroll
        for (int kt = 0; kt < 7; kt++) {
            const int kw = kt * 8;
            uint32_t a[4];
            a[0] = sm[G2_A + (r0 + g) * WS + kw + tg];
            a[1] = sm[G2_A + (r0 + g + 8) * WS + kw + tg];
            a[2] = sm[G2_A + (r0 + g) * WS + kw + 4 + tg];
            a[3] = sm[G2_A + (r0 + g + 8) * WS + kw + 4 + tg];
            #pragma unroll
            for (int nt = 0; nt < 13; nt++) {
                const int n0 = nt * 8;
                uint32_t bh[2], bl[2];
                bh[0] = sm[G2_BHI + (n0 + g) * WS + kw + tg];
                bh[1] = sm[G2_BHI + (n0 + g) * WS + kw + 4 + tg];
                bl[0] = sm[G2_BLO + (n0 + g) * WS + kw + tg];
                bl[1] = sm[G2_BLO + (n0 + g) * WS + kw + 4 + tg];
                mma_f16(acc[nt], a, bh);
                mma_f16(acc2[nt], a, bl);
            }
        }

        const int row1 = i0 + r0 + g, row2 = row1 + 8;
        const float s1 = (row1 < NN) ? d_dis[row1] : 0.f;
        const float s2 = (row2 < NN) ? d_dis[row2] : 0.f;
        const float inv = 1.0f / 2048.0f;
        #pragma unroll
        for (int nt = 0; nt < 13; nt++) {
            const int c = nt * 8 + 2 * tg;
            if (c < C) {
                if (row1 < NN) {
                    float v0 = acc[nt][0] + acc2[nt][0] * inv;
                    float v1 = acc[nt][1] + acc2[nt][1] * inv;
                    *(__half2*)&d_G16[(size_t)row1 * C + c] =
                        __floats2half2_rn(s1 * v0, s1 * v1);
                }
                if (row2 < NN) {
                    float v2 = acc[nt][2] + acc2[nt][2] * inv;
                    float v3 = acc[nt][3] + acc2[nt][3] * inv;
                    *(__half2*)&d_G16[(size_t)row2 * C + c] =
                        __floats2half2_rn(s2 * v2, s2 * v3);
                }
            }
        }
        __syncthreads();
    }
}

// ---------------- gather + epilogues ----------------
__device__ __forceinline__ float4 ldg_h4(const __half* p) {
    uint2 r = *(const uint2*)p;
    __half2 a = *reinterpret_cast<__half2*>(&r.x);
    __half2 b = *reinterpret_cast<__half2*>(&r.y);
    float2 f0 = __half22float2(a), f1 = __half22float2(b);
    return make_float4(f0.x, f0.y, f1.x, f1.y);
}

__global__ void k_gather(int mode, const float* __restrict__ b1,
                         const float* __restrict__ bmu, const float* __restrict__ bls,
                         float* __restrict__ out) {
    int w = (blockIdx.x * blockDim.x + threadIdx.x) >> 5;
    int lane = threadIdx.x & 31;
    if (mode == 1 && blockIdx.x == 0 && threadIdx.x == 0) d_total = 0;  // reset for next run
    if (w >= NN || lane >= 25) return;
    int en = d_start[w];
    int n  = d_cnt[w];
    if (mode == 1 && lane == 0) d_cnt[w] = 0;   // reset for next run (after read)
    int st = en - n;
    int p4 = lane * 4;

    float4 acc = ldg_h4(&d_G16[(size_t)w * C + p4]);   // self-loop term
    for (int j = 0; j < n; j++) {
        int s = d_csr[st + j];
        float4 v = ldg_h4(&d_G16[(size_t)s * C + p4]);
        acc.x += v.x; acc.y += v.y; acc.z += v.z; acc.w += v.w;
    }
    float sc = d_dis[w];

    if (mode == 0) {
        float4 bb = *(const float4*)&b1[p4];
        __half2 h0 = __floats2half2_rn(fmaxf(fmaf(sc, acc.x, bb.x), 0.f),
                                       fmaxf(fmaf(sc, acc.y, bb.y), 0.f));
        __half2 h1 = __floats2half2_rn(fmaxf(fmaf(sc, acc.z, bb.z), 0.f),
                                       fmaxf(fmaf(sc, acc.w, bb.w), 0.f));
        uint2 packed;
        packed.x = *reinterpret_cast<uint32_t*>(&h0);
        packed.y = *reinterpret_cast<uint32_t*>(&h1);
        *(uint2*)&d_H16[(size_t)w * C + p4] = packed;
    } else {
        float v[4] = { sc * acc.x, sc * acc.y, sc * acc.z, sc * acc.w };
        #pragma unroll
        for (int q = 0; q < 4; q++) {
            int c = p4 + q;
            if (c < OC) out[(size_t)w * OC + c]                          = v[q] + bmu[c];
            else        out[(size_t)NN * OC + (size_t)w * OC + (c - OC)] = v[q] + bls[c - OC];
        }
    }
}

extern "C" void kernel_launch(void* const* d_in, const int* in_sizes, int n_in,
                              void* d_out, int out_size) {
    const float* x   = (const float*)d_in[0];
    const int*   ei  = (const int*)  d_in[1];
    const float* W1  = (const float*)d_in[2];
    const float* b1  = (const float*)d_in[3];
    const float* Wmu = (const float*)d_in[4];
    const float* bmu = (const float*)d_in[5];
    const float* Wls = (const float*)d_in[6];
    const float* bls = (const float*)d_in[7];
    float* out = (float*)d_out;

    const int* src = ei;
    const int* dst = ei + NE;

    cudaFuncSetAttribute(k_gemm1, cudaFuncAttributeMaxDynamicSharedMemorySize, G1_WORDS * 4);
    cudaFuncSetAttribute(k_gemm2, cudaFuncAttributeMaxDynamicSharedMemorySize, G2_WORDS * 4);

    // CSR build (d_cnt/d_total arrive zeroed: load-time init or prior run's reset)
    k_deg<<<(NE + 255) / 256, 256>>>(dst);
    k_alloc<<<(NN + 1023) / 1024, 1024>>>();
    k_fill<<<(NE + 255) / 256, 256>>>(src, dst);

    // layer 1
    k_gemm1<<<GEMM_GRID, GEMM_THREADS, G1_WORDS * 4>>>(x, W1);
    k_gather<<<(NN * 32 + 255) / 256, 256>>>(0, b1, nullptr, nullptr, nullptr);

    // layers 2+3 fused (mu | logstd column-concat)
    k_gemm2<<<GEMM_GRID, GEMM_THREADS, G2_WORDS * 4>>>(Wmu, Wls);
    k_gather<<<(NN * 32 + 255) / 256, 256>>>(1, nullptr, bmu, bls, out);
}

// round 8
// speedup vs baseline: 1.0424x; 1.0424x over previous
#include <cuda_runtime.h>
#include <cuda_fp16.h>
#include <stdint.h>

#define NN 100000
#define NE 800000
#define C  100
#define OC 50

#define TM 256
#define NTILES ((NN + TM - 1) / TM)
#define GEMM_GRID 148
#define GEMM_THREADS 512

// word stride per row: data 50 words (100 halves), reads touch words 0..55,
// WS=60 -> (60*g + tg) mod 32 distinct for g 0..7, tg 0..3 => conflict-free
#define WS 60
#define SA 0
#define SBHI (TM * WS)                 // 15360
#define SBLO (SBHI + 104 * WS)         // 21600
#define SM_WORDS (SBLO + 104 * WS)     // 27840 words = 111360 B

// ---------------- device globals (scratch; zero-initialized at load) ----------------
__device__ __align__(16) float d_dis[NN];
__device__ __align__(16) __half d_G16[NN * C];
__device__ __align__(16) __half d_H16[NN * C];
__device__ int d_cnt[NN];      // re-zeroed at end of every run (gather mode 1)
__device__ int d_start[NN];    // after k_fill: END pointers
__device__ int d_csr[NE];
__device__ int d_total;        // re-zeroed at end of every run

// ---------------- mma helper (baseline PTX, sm_80+) ----------------
__device__ __forceinline__ void mma_f16(float* d, const uint32_t* a, const uint32_t* b) {
    asm volatile(
        "mma.sync.aligned.m16n8k16.row.col.f32.f16.f16.f32 "
        "{%0,%1,%2,%3}, {%4,%5,%6,%7}, {%8,%9}, {%0,%1,%2,%3};"
        : "+f"(d[0]), "+f"(d[1]), "+f"(d[2]), "+f"(d[3])
        : "r"(a[0]), "r"(a[1]), "r"(a[2]), "r"(a[3]), "r"(b[0]), "r"(b[1]));
}

// ---------------- CSR build ----------------
__global__ void k_deg(const int* __restrict__ dst) {
    int e = blockIdx.x * blockDim.x + threadIdx.x;
    if (e < NE) atomicAdd(&d_cnt[dst[e]], 1);    // d_cnt pre-zeroed
}

__global__ void k_alloc() {   // block scan + one global atomic; also dis
    __shared__ int sh[1024];
    __shared__ int sbase;
    int i = blockIdx.x * 1024 + threadIdx.x;
    int v = (i < NN) ? d_cnt[i] : 0;
    sh[threadIdx.x] = v;
    __syncthreads();
    for (int off = 1; off < 1024; off <<= 1) {
        int t = (threadIdx.x >= off) ? sh[threadIdx.x - off] : 0;
        __syncthreads();
        sh[threadIdx.x] += t;
        __syncthreads();
    }
    if (threadIdx.x == 1023) sbase = atomicAdd(&d_total, sh[1023]);
    __syncthreads();
    if (i < NN) {
        d_start[i] = sbase + sh[threadIdx.x] - v;
        d_dis[i] = rsqrtf((float)v + 1.0f);
    }
}

__global__ void k_fill(const int* __restrict__ src, const int* __restrict__ dst) {
    int e = blockIdx.x * blockDim.x + threadIdx.x;
    if (e >= NE) return;
    int d = dst[e];
    int p = atomicAdd(&d_start[d], 1);   // start[] becomes END pointers
    d_csr[p] = src[e];
}

// ---------------- unified fp16 2-pass GEMM: G16 = dis[row] * (A @ W) ----------------
// B = Whi + (Wlo*2048)*2^-11 (fp16 hi/lo, lo folded per k-step via 4-reg temp).
// mode 0: A = x fp32 -> fp16 (err ~2^-12); W = W0 [C x C]
// mode 1: A = d_H16 raw fp16 (exact);      W = [Wa | Wb] column-concat
__global__ void __launch_bounds__(GEMM_THREADS, 1)
k_gemm(const float* __restrict__ Ain, const float* __restrict__ W0,
       const float* __restrict__ Wa, const float* __restrict__ Wb, int mode) {
    extern __shared__ uint32_t sm[];
    const int tid = threadIdx.x, wid = tid >> 5, lane = tid & 31;
    const int g = lane >> 2, tg = lane & 3;

    for (int i = tid; i < SM_WORDS; i += GEMM_THREADS) sm[i] = 0;
    __syncthreads();

    // stage W -> fp16 hi/lo; layout B[n][kword]
    for (int idx = tid; idx < C * C; idx += GEMM_THREADS) {
        int k = idx / C, n = idx % C;
        float w = (mode == 0) ? W0[idx]
                              : ((n < OC) ? Wa[k * OC + n] : Wb[k * OC + (n - OC)]);
        __half hi = __float2half_rn(w);
        __half lo = __float2half_rn((w - __half2float(hi)) * 2048.0f);
        ((__half*)(sm + SBHI))[(n * WS + (k >> 1)) * 2 + (k & 1)] = hi;
        ((__half*)(sm + SBLO))[(n * WS + (k >> 1)) * 2 + (k & 1)] = lo;
    }
    __syncthreads();

    const int r0 = wid * 16;   // 16 warps x 16 rows = 256

    for (int t = blockIdx.x; t < NTILES; t += gridDim.x) {
        const int i0 = t * TM;
        const int rowlim = NN - i0;

        // stage A tile [256 x 100] as fp16 words
        for (int q = tid; q < TM * 25; q += GEMM_THREADS) {
            int r = q / 25, c4 = (q % 25) * 4;
            uint2 w2;
            if (r < rowlim) {
                if (mode == 0) {
                    float4 v = *(const float4*)&Ain[(size_t)(i0 + r) * C + c4];
                    __half2 h0 = __floats2half2_rn(v.x, v.y);
                    __half2 h1 = __floats2half2_rn(v.z, v.w);
                    w2.x = *reinterpret_cast<uint32_t*>(&h0);
                    w2.y = *reinterpret_cast<uint32_t*>(&h1);
                } else {
                    w2 = *(const uint2*)&d_H16[(size_t)(i0 + r) * C + c4];
                }
            } else {
                w2 = make_uint2(0u, 0u);
            }
            *(uint2*)(sm + SA + r * WS + (c4 >> 1)) = w2;
        }
        __syncthreads();

        float acc[13][4];
        #pragma unroll
        for (int nt = 0; nt < 13; nt++)
            #pragma unroll
            for (int q = 0; q < 4; q++) acc[nt][q] = 0.f;

        const float inv = 1.0f / 2048.0f;
        #pragma unroll
        for (int kt = 0; kt < 7; kt++) {
            const int kw = kt * 8;
            uint32_t a[4];
            a[0] = sm[SA + (r0 + g) * WS + kw + tg];
            a[1] = sm[SA + (r0 + g + 8) * WS + kw + tg];
            a[2] = sm[SA + (r0 + g) * WS + kw + 4 + tg];
            a[3] = sm[SA + (r0 + g + 8) * WS + kw + 4 + tg];
            #pragma unroll
            for (int nt = 0; nt < 13; nt++) {
                const int n0 = nt * 8;
                uint32_t bh[2], bl[2];
                bh[0] = sm[SBHI + (n0 + g) * WS + kw + tg];
                bh[1] = sm[SBHI + (n0 + g) * WS + kw + 4 + tg];
                bl[0] = sm[SBLO + (n0 + g) * WS + kw + tg];
                bl[1] = sm[SBLO + (n0 + g) * WS + kw + 4 + tg];
                mma_f16(acc[nt], a, bh);
                float t2[4] = {0.f, 0.f, 0.f, 0.f};     // 4-reg temp, no spill
                mma_f16(t2, a, bl);
                #pragma unroll
                for (int q = 0; q < 4; q++)
                    acc[nt][q] = fmaf(t2[q], inv, acc[nt][q]);
            }
        }

        const int row1 = i0 + r0 + g, row2 = row1 + 8;
        const float s1 = (row1 < NN) ? d_dis[row1] : 0.f;
        const float s2 = (row2 < NN) ? d_dis[row2] : 0.f;
        #pragma unroll
        for (int nt = 0; nt < 13; nt++) {
            const int c = nt * 8 + 2 * tg;
            if (c < C) {
                if (row1 < NN)
                    *(__half2*)&d_G16[(size_t)row1 * C + c] =
                        __floats2half2_rn(s1 * acc[nt][0], s1 * acc[nt][1]);
                if (row2 < NN)
                    *(__half2*)&d_G16[(size_t)row2 * C + c] =
                        __floats2half2_rn(s2 * acc[nt][2], s2 * acc[nt][3]);
            }
        }
        __syncthreads();
    }
}

// ---------------- gather + epilogues ----------------
__device__ __forceinline__ float4 ldg_h4(const __half* p) {
    uint2 r = *(const uint2*)p;
    __half2 a = *reinterpret_cast<__half2*>(&r.x);
    __half2 b = *reinterpret_cast<__half2*>(&r.y);
    float2 f0 = __half22float2(a), f1 = __half22float2(b);
    return make_float4(f0.x, f0.y, f1.x, f1.y);
}

__global__ void k_gather(int mode, const float* __restrict__ b1,
                         const float* __restrict__ bmu, const float* __restrict__ bls,
                         float* __restrict__ out) {
    int w = (blockIdx.x * blockDim.x + threadIdx.x) >> 5;
    int lane = threadIdx.x & 31;
    if (mode == 1 && blockIdx.x == 0 && threadIdx.x == 0) d_total = 0;  // reset
    if (w >= NN || lane >= 25) return;
    int en = d_start[w];
    int n  = d_cnt[w];
    if (mode == 1 && lane == 0) d_cnt[w] = 0;   // reset for next graph replay
    int st = en - n;
    int p4 = lane * 4;

    float4 acc = ldg_h4(&d_G16[(size_t)w * C + p4]);   // self-loop term
    for (int j = 0; j < n; j++) {
        int s = d_csr[st + j];
        float4 v = ldg_h4(&d_G16[(size_t)s * C + p4]);
        acc.x += v.x; acc.y += v.y; acc.z += v.z; acc.w += v.w;
    }
    float sc = d_dis[w];

    if (mode == 0) {
        float4 bb = *(const float4*)&b1[p4];
        __half2 h0 = __floats2half2_rn(fmaxf(fmaf(sc, acc.x, bb.x), 0.f),
                                       fmaxf(fmaf(sc, acc.y, bb.y), 0.f));
        __half2 h1 = __floats2half2_rn(fmaxf(fmaf(sc, acc.z, bb.z), 0.f),
                                       fmaxf(fmaf(sc, acc.w, bb.w), 0.f));
        uint2 packed;
        packed.x = *reinterpret_cast<uint32_t*>(&h0);
        packed.y = *reinterpret_cast<uint32_t*>(&h1);
        *(uint2*)&d_H16[(size_t)w * C + p4] = packed;
    } else {
        float v[4] = { sc * acc.x, sc * acc.y, sc * acc.z, sc * acc.w };
        #pragma unroll
        for (int q = 0; q < 4; q++) {
            int c = p4 + q;
            if (c < OC) out[(size_t)w * OC + c]                          = v[q] + bmu[c];
            else        out[(size_t)NN * OC + (size_t)w * OC + (c - OC)] = v[q] + bls[c - OC];
        }
    }
}

extern "C" void kernel_launch(void* const* d_in, const int* in_sizes, int n_in,
                              void* d_out, int out_size) {
    const float* x   = (const float*)d_in[0];
    const int*   ei  = (const int*)  d_in[1];
    const float* W1  = (const float*)d_in[2];
    const float* b1  = (const float*)d_in[3];
    const float* Wmu = (const float*)d_in[4];
    const float* bmu = (const float*)d_in[5];
    const float* Wls = (const float*)d_in[6];
    const float* bls = (const float*)d_in[7];
    float* out = (float*)d_out;

    const int* src = ei;
    const int* dst = ei + NE;

    cudaFuncSetAttribute(k_gemm, cudaFuncAttributeMaxDynamicSharedMemorySize, SM_WORDS * 4);

    // CSR build
    k_deg<<<(NE + 255) / 256, 256>>>(dst);
    k_alloc<<<(NN + 1023) / 1024, 1024>>>();
    k_fill<<<(NE + 255) / 256, 256>>>(src, dst);

    // layer 1
    k_gemm<<<GEMM_GRID, GEMM_THREADS, SM_WORDS * 4>>>(x, W1, nullptr, nullptr, 0);
    k_gather<<<(NN * 32 + 255) / 256, 256>>>(0, b1, nullptr, nullptr, nullptr);

    // layers 2+3 fused (mu | logstd column-concat)
    k_gemm<<<GEMM_GRID, GEMM_THREADS, SM_WORDS * 4>>>(nullptr, nullptr, Wmu, Wls, 1);
    k_gather<<<(NN * 32 + 255) / 256, 256>>>(1, nullptr, bmu, bls, out);
}

// round 9
// speedup vs baseline: 1.6465x; 1.5795x over previous
#include <cuda_runtime.h>
#include <cuda_fp16.h>
#include <stdint.h>

#define NN 100000
#define NE 800000
#define C  100
#define OC 50
#define NBLK ((NN + 1023) / 1024)

#define TM 128
#define NTILES ((NN + TM - 1) / TM)
#define GEMM_GRID 296            // 2 CTAs per SM
#define GEMM_THREADS 256

// word stride per row: reads touch words 0..55; WS=60 -> conflict-free frags
#define WS 60
#define SA 0
#define SBHI (TM * WS)                 // 7680
#define SBLO (SBHI + 104 * WS)         // 13920
#define SM_WORDS (SBLO + 104 * WS)     // 20160 words = 80640 B  (2 CTAs/SM)

// ---------------- device globals (scratch) ----------------
__device__ __align__(16) float d_dis[NN];
__device__ __align__(16) __half d_G16[NN * C];
__device__ __align__(16) __half d_H16[NN * C];
__device__ int d_cnt[NN];
__device__ int d_start[NN];   // after k_fill: END pointers
__device__ int d_csr[NE];
__device__ int d_bsum[NBLK + 1];

// ---------------- mma helper (baseline PTX, sm_80+) ----------------
__device__ __forceinline__ void mma_f16(float* d, const uint32_t* a, const uint32_t* b) {
    asm volatile(
        "mma.sync.aligned.m16n8k16.row.col.f32.f16.f16.f32 "
        "{%0,%1,%2,%3}, {%4,%5,%6,%7}, {%8,%9}, {%0,%1,%2,%3};"
        : "+f"(d[0]), "+f"(d[1]), "+f"(d[2]), "+f"(d[3])
        : "r"(a[0]), "r"(a[1]), "r"(a[2]), "r"(a[3]), "r"(b[0]), "r"(b[1]));
}

// ---------------- CSR build (round-6 scheme, known good) ----------------
__global__ void k_zero() {
    int i = blockIdx.x * blockDim.x + threadIdx.x;
    if (i < NN) d_cnt[i] = 0;
}
__global__ void k_deg(const int* __restrict__ dst) {
    int e = blockIdx.x * blockDim.x + threadIdx.x;
    if (e < NE) atomicAdd(&d_cnt[dst[e]], 1);
}
__global__ void k_scan1() {   // block-local exclusive scan + dis = rsqrt(cnt+1)
    __shared__ int sh[1024];
    int i = blockIdx.x * 1024 + threadIdx.x;
    int v = (i < NN) ? d_cnt[i] : 0;
    sh[threadIdx.x] = v;
    __syncthreads();
    for (int off = 1; off < 1024; off <<= 1) {
        int t = (threadIdx.x >= off) ? sh[threadIdx.x - off] : 0;
        __syncthreads();
        sh[threadIdx.x] += t;
        __syncthreads();
    }
    if (i < NN) {
        d_start[i] = sh[threadIdx.x] - v;
        d_dis[i] = rsqrtf((float)v + 1.0f);
    }
    if (threadIdx.x == 1023) d_bsum[blockIdx.x] = sh[1023];
}
__global__ void k_scan23() {   // every block redundantly scans the 98 partials
    __shared__ int sh[128];
    int t = threadIdx.x;
    sh[t] = (t < NBLK) ? d_bsum[t] : 0;
    __syncthreads();
    for (int off = 1; off < 128; off <<= 1) {
        int u = (t >= off) ? sh[t - off] : 0;
        __syncthreads();
        sh[t] += u;
        __syncthreads();
    }
    for (int q = 0; q < 2; q++) {
        int idx = blockIdx.x * 256 + q * 128 + t;
        if (idx < NN) {
            int blk = idx >> 10;
            int boff = (blk > 0) ? sh[blk - 1] : 0;
            d_start[idx] += boff;
        }
    }
}
__global__ void k_fill(const int* __restrict__ src, const int* __restrict__ dst) {
    int e = blockIdx.x * blockDim.x + threadIdx.x;
    if (e >= NE) return;
    int d = dst[e];
    int p = atomicAdd(&d_start[d], 1);   // start[] becomes END pointers
    d_csr[p] = src[e];
}

// ---------------- unified fp16 2-pass GEMM: G16 = dis[row] * (A @ W) ----------------
// B = Whi + (Wlo*2048)*2^-11, lo-pass folded per k-step via 4-reg temp (no spill).
// mode 0: A = x fp32 -> fp16; W = W0 [C x C]
// mode 1: A = d_H16 raw fp16; W = [Wa | Wb] column-concat
__global__ void __launch_bounds__(GEMM_THREADS, 2)
k_gemm(const float* __restrict__ Ain, const float* __restrict__ W0,
       const float* __restrict__ Wa, const float* __restrict__ Wb, int mode) {
    extern __shared__ uint32_t sm[];
    const int tid = threadIdx.x, wid = tid >> 5, lane = tid & 31;
    const int g = lane >> 2, tg = lane & 3;

    for (int i = tid; i < SM_WORDS; i += GEMM_THREADS) sm[i] = 0;
    __syncthreads();

    // stage W -> fp16 hi/lo; layout B[n][kword]
    for (int idx = tid; idx < C * C; idx += GEMM_THREADS) {
        int k = idx / C, n = idx % C;
        float w = (mode == 0) ? W0[idx]
                              : ((n < OC) ? Wa[k * OC + n] : Wb[k * OC + (n - OC)]);
        __half hi = __float2half_rn(w);
        __half lo = __float2half_rn((w - __half2float(hi)) * 2048.0f);
        ((__half*)(sm + SBHI))[(n * WS + (k >> 1)) * 2 + (k & 1)] = hi;
        ((__half*)(sm + SBLO))[(n * WS + (k >> 1)) * 2 + (k & 1)] = lo;
    }
    __syncthreads();

    const int r0 = wid * 16;   // 8 warps x 16 rows = 128

    for (int t = blockIdx.x; t < NTILES; t += gridDim.x) {
        const int i0 = t * TM;
        const int rowlim = NN - i0;

        // stage A tile [128 x 100] as fp16 words
        for (int q = tid; q < TM * 25; q += GEMM_THREADS) {
            int r = q / 25, c4 = (q % 25) * 4;
            uint2 w2;
            if (r < rowlim) {
                if (mode == 0) {
                    float4 v = *(const float4*)&Ain[(size_t)(i0 + r) * C + c4];
                    __half2 h0 = __floats2half2_rn(v.x, v.y);
                    __half2 h1 = __floats2half2_rn(v.z, v.w);
                    w2.x = *reinterpret_cast<uint32_t*>(&h0);
                    w2.y = *reinterpret_cast<uint32_t*>(&h1);
                } else {
                    w2 = *(const uint2*)&d_H16[(size_t)(i0 + r) * C + c4];
                }
            } else {
                w2 = make_uint2(0u, 0u);
            }
            *(uint2*)(sm + SA + r * WS + (c4 >> 1)) = w2;
        }
        __syncthreads();

        float acc[13][4];
        #pragma unroll
        for (int nt = 0; nt < 13; nt++)
            #pragma unroll
            for (int q = 0; q < 4; q++) acc[nt][q] = 0.f;

        const float inv = 1.0f / 2048.0f;
        #pragma unroll
        for (int kt = 0; kt < 7; kt++) {
            const int kw = kt * 8;
            uint32_t a[4];
            a[0] = sm[SA + (r0 + g) * WS + kw + tg];
            a[1] = sm[SA + (r0 + g + 8) * WS + kw + tg];
            a[2] = sm[SA + (r0 + g) * WS + kw + 4 + tg];
            a[3] = sm[SA + (r0 + g + 8) * WS + kw + 4 + tg];
            #pragma unroll
            for (int nt = 0; nt < 13; nt++) {
                const int n0 = nt * 8;
                uint32_t bh[2], bl[2];
                bh[0] = sm[SBHI + (n0 + g) * WS + kw + tg];
                bh[1] = sm[SBHI + (n0 + g) * WS + kw + 4 + tg];
                bl[0] = sm[SBLO + (n0 + g) * WS + kw + tg];
                bl[1] = sm[SBLO + (n0 + g) * WS + kw + 4 + tg];
                mma_f16(acc[nt], a, bh);
                float t2[4] = {0.f, 0.f, 0.f, 0.f};
                mma_f16(t2, a, bl);
                #pragma unroll
                for (int q = 0; q < 4; q++)
                    acc[nt][q] = fmaf(t2[q], inv, acc[nt][q]);
            }
        }

        const int row1 = i0 + r0 + g, row2 = row1 + 8;
        const float s1 = (row1 < NN) ? d_dis[row1] : 0.f;
        const float s2 = (row2 < NN) ? d_dis[row2] : 0.f;
        #pragma unroll
        for (int nt = 0; nt < 13; nt++) {
            const int c = nt * 8 + 2 * tg;
            if (c < C) {
                if (row1 < NN)
                    *(__half2*)&d_G16[(size_t)row1 * C + c] =
                        __floats2half2_rn(s1 * acc[nt][0], s1 * acc[nt][1]);
                if (row2 < NN)
                    *(__half2*)&d_G16[(size_t)row2 * C + c] =
                        __floats2half2_rn(s2 * acc[nt][2], s2 * acc[nt][3]);
            }
        }
        __syncthreads();
    }
}

// ---------------- gather + epilogues (round-6 verbatim) ----------------
__device__ __forceinline__ float4 ldg_h4(const __half* p) {
    uint2 r = *(const uint2*)p;
    __half2 a = *reinterpret_cast<__half2*>(&r.x);
    __half2 b = *reinterpret_cast<__half2*>(&r.y);
    float2 f0 = __half22float2(a), f1 = __half22float2(b);
    return make_float4(f0.x, f0.y, f1.x, f1.y);
}

__global__ void k_gather(int mode, const float* __restrict__ b1,
                         const float* __restrict__ bmu, const float* __restrict__ bls,
                         float* __restrict__ out) {
    int w = (blockIdx.x * blockDim.x + threadIdx.x) >> 5;
    int lane = threadIdx.x & 31;
    if (w >= NN || lane >= 25) return;
    int en = d_start[w];
    int n  = d_cnt[w];
    int st = en - n;
    int p4 = lane * 4;

    float4 acc = ldg_h4(&d_G16[(size_t)w * C + p4]);   // self-loop term
    for (int j = 0; j < n; j++) {
        int s = d_csr[st + j];
        float4 v = ldg_h4(&d_G16[(size_t)s * C + p4]);
        acc.x += v.x; acc.y += v.y; acc.z += v.z; acc.w += v.w;
    }
    float sc = d_dis[w];

    if (mode == 0) {
        float4 bb = *(const float4*)&b1[p4];
        __half2 h0 = __floats2half2_rn(fmaxf(fmaf(sc, acc.x, bb.x), 0.f),
                                       fmaxf(fmaf(sc, acc.y, bb.y), 0.f));
        __half2 h1 = __floats2half2_rn(fmaxf(fmaf(sc, acc.z, bb.z), 0.f),
                                       fmaxf(fmaf(sc, acc.w, bb.w), 0.f));
        uint2 packed;
        packed.x = *reinterpret_cast<uint32_t*>(&h0);
        packed.y = *reinterpret_cast<uint32_t*>(&h1);
        *(uint2*)&d_H16[(size_t)w * C + p4] = packed;
    } else {
        float v[4] = { sc * acc.x, sc * acc.y, sc * acc.z, sc * acc.w };
        #pragma unroll
        for (int q = 0; q < 4; q++) {
            int c = p4 + q;
            if (c < OC) out[(size_t)w * OC + c]                          = v[q] + bmu[c];
            else        out[(size_t)NN * OC + (size_t)w * OC + (c - OC)] = v[q] + bls[c - OC];
        }
    }
}

extern "C" void kernel_launch(void* const* d_in, const int* in_sizes, int n_in,
                              void* d_out, int out_size) {
    const float* x   = (const float*)d_in[0];
    const int*   ei  = (const int*)  d_in[1];
    const float* W1  = (const float*)d_in[2];
    const float* b1  = (const float*)d_in[3];
    const float* Wmu = (const float*)d_in[4];
    const float* bmu = (const float*)d_in[5];
    const float* Wls = (const float*)d_in[6];
    const float* bls = (const float*)d_in[7];
    float* out = (float*)d_out;

    const int* src = ei;
    const int* dst = ei + NE;

    cudaFuncSetAttribute(k_gemm, cudaFuncAttributeMaxDynamicSharedMemorySize, SM_WORDS * 4);

    // CSR build (round-6 scheme)
    k_zero<<<(NN + 255) / 256, 256>>>();
    k_deg<<<(NE + 255) / 256, 256>>>(dst);
    k_scan1<<<NBLK, 1024>>>();
    k_scan23<<<(NN + 255) / 256, 128>>>();
    k_fill<<<(NE + 255) / 256, 256>>>(src, dst);

    // layer 1
    k_gemm<<<GEMM_GRID, GEMM_THREADS, SM_WORDS * 4>>>(x, W1, nullptr, nullptr, 0);
    k_gather<<<(NN * 32 + 255) / 256, 256>>>(0, b1, nullptr, nullptr, nullptr);

    // layers 2+3 fused (mu | logstd column-concat)
    k_gemm<<<GEMM_GRID, GEMM_THREADS, SM_WORDS * 4>>>(nullptr, nullptr, Wmu, Wls, 1);
    k_gather<<<(NN * 32 + 255) / 256, 256>>>(1, nullptr, bmu, bls, out);
}

// round 10
// speedup vs baseline: 1.7147x; 1.0415x over previous
#include <cuda_runtime.h>
#include <cuda_fp16.h>
#include <stdint.h>

#define NN 100000
#define NE 800000
#define C  100
#define OC 50
#define NBLK ((NN + 1023) / 1024)

#define TM 128
#define NTILES ((NN + TM - 1) / TM)
#define GEMM_GRID 296            // 2 CTAs per SM
#define GEMM_THREADS 256

// word stride per row: reads touch words 0..55; WS=60 -> conflict-free frags
#define WS 60
#define SA 0
#define SB (TM * WS)                   // 7680
#define SM_WORDS (SB + 104 * WS)       // 13920 words = 55680 B (2 CTAs/SM easy)

// ---------------- device globals (scratch; zero-init at load) ----------------
__device__ __align__(16) float d_dis[NN];
__device__ __align__(16) __half d_G16[NN * C];
__device__ __align__(16) __half d_H16[NN * C];
__device__ int d_cnt[NN];      // re-zeroed at tail of gather mode 1 each run
__device__ int d_start[NN];    // after k_fill: END pointers
__device__ int d_csr[NE];
__device__ int d_bsum[NBLK + 1];

// ---------------- mma helper (baseline PTX, sm_80+) ----------------
__device__ __forceinline__ void mma_f16(float* d, const uint32_t* a, const uint32_t* b) {
    asm volatile(
        "mma.sync.aligned.m16n8k16.row.col.f32.f16.f16.f32 "
        "{%0,%1,%2,%3}, {%4,%5,%6,%7}, {%8,%9}, {%0,%1,%2,%3};"
        : "+f"(d[0]), "+f"(d[1]), "+f"(d[2]), "+f"(d[3])
        : "r"(a[0]), "r"(a[1]), "r"(a[2]), "r"(a[3]), "r"(b[0]), "r"(b[1]));
}

// ---------------- CSR build ----------------
__global__ void k_deg(const int* __restrict__ dst) {
    int e = blockIdx.x * blockDim.x + threadIdx.x;
    if (e < NE) atomicAdd(&d_cnt[dst[e]], 1);    // cnt pre-zeroed (load / prior run)
}
__global__ void k_scan1() {   // block-local exclusive scan + dis = rsqrt(cnt+1)
    __shared__ int sh[1024];
    int i = blockIdx.x * 1024 + threadIdx.x;
    int v = (i < NN) ? d_cnt[i] : 0;
    sh[threadIdx.x] = v;
    __syncthreads();
    for (int off = 1; off < 1024; off <<= 1) {
        int t = (threadIdx.x >= off) ? sh[threadIdx.x - off] : 0;
        __syncthreads();
        sh[threadIdx.x] += t;
        __syncthreads();
    }
    if (i < NN) {
        d_start[i] = sh[threadIdx.x] - v;
        d_dis[i] = rsqrtf((float)v + 1.0f);
    }
    if (threadIdx.x == 1023) d_bsum[blockIdx.x] = sh[1023];
}
__global__ void k_scan23() {   // every block redundantly scans the 98 partials
    __shared__ int sh[128];
    int t = threadIdx.x;
    sh[t] = (t < NBLK) ? d_bsum[t] : 0;
    __syncthreads();
    for (int off = 1; off < 128; off <<= 1) {
        int u = (t >= off) ? sh[t - off] : 0;
        __syncthreads();
        sh[t] += u;
        __syncthreads();
    }
    for (int q = 0; q < 2; q++) {
        int idx = blockIdx.x * 256 + q * 128 + t;
        if (idx < NN) {
            int blk = idx >> 10;
            int boff = (blk > 0) ? sh[blk - 1] : 0;
            d_start[idx] += boff;
        }
    }
}
__global__ void k_fill(const int* __restrict__ src, const int* __restrict__ dst) {
    int e = blockIdx.x * blockDim.x + threadIdx.x;
    if (e >= NE) return;
    int d = dst[e];
    int p = atomicAdd(&d_start[d], 1);   // start[] becomes END pointers
    d_csr[p] = src[e];
}

// ---------------- single-pass fp16 GEMM: G16 = dis[row] * (A @ W) ----------------
// mode 0: A = x fp32 -> fp16; W = W0 [C x C]
// mode 1: A = d_H16 raw fp16; W = [Wa | Wb] column-concat
__global__ void __launch_bounds__(GEMM_THREADS, 2)
k_gemm(const float* __restrict__ Ain, const float* __restrict__ W0,
       const float* __restrict__ Wa, const float* __restrict__ Wb, int mode) {
    extern __shared__ uint32_t sm[];
    const int tid = threadIdx.x, wid = tid >> 5, lane = tid & 31;
    const int g = lane >> 2, tg = lane & 3;

    for (int i = tid; i < SM_WORDS; i += GEMM_THREADS) sm[i] = 0;
    __syncthreads();

    // stage W -> fp16; layout B[n][kword]
    for (int idx = tid; idx < C * C; idx += GEMM_THREADS) {
        int k = idx / C, n = idx % C;
        float w = (mode == 0) ? W0[idx]
                              : ((n < OC) ? Wa[k * OC + n] : Wb[k * OC + (n - OC)]);
        ((__half*)(sm + SB))[(n * WS + (k >> 1)) * 2 + (k & 1)] = __float2half_rn(w);
    }
    __syncthreads();

    const int r0 = wid * 16;   // 8 warps x 16 rows = 128

    for (int t = blockIdx.x; t < NTILES; t += gridDim.x) {
        const int i0 = t * TM;
        const int rowlim = NN - i0;

        // stage A tile [128 x 100] as fp16 words
        for (int q = tid; q < TM * 25; q += GEMM_THREADS) {
            int r = q / 25, c4 = (q % 25) * 4;
            uint2 w2;
            if (r < rowlim) {
                if (mode == 0) {
                    float4 v = *(const float4*)&Ain[(size_t)(i0 + r) * C + c4];
                    __half2 h0 = __floats2half2_rn(v.x, v.y);
                    __half2 h1 = __floats2half2_rn(v.z, v.w);
                    w2.x = *reinterpret_cast<uint32_t*>(&h0);
                    w2.y = *reinterpret_cast<uint32_t*>(&h1);
                } else {
                    w2 = *(const uint2*)&d_H16[(size_t)(i0 + r) * C + c4];
                }
            } else {
                w2 = make_uint2(0u, 0u);
            }
            *(uint2*)(sm + SA + r * WS + (c4 >> 1)) = w2;
        }
        __syncthreads();

        float acc[13][4];
        #pragma unroll
        for (int nt = 0; nt < 13; nt++)
            #pragma unroll
            for (int q = 0; q < 4; q++) acc[nt][q] = 0.f;

        #pragma unroll
        for (int kt = 0; kt < 7; kt++) {
            const int kw = kt * 8;
            uint32_t a[4];
            a[0] = sm[SA + (r0 + g) * WS + kw + tg];
            a[1] = sm[SA + (r0 + g + 8) * WS + kw + tg];
            a[2] = sm[SA + (r0 + g) * WS + kw + 4 + tg];
            a[3] = sm[SA + (r0 + g + 8) * WS + kw + 4 + tg];
            #pragma unroll
            for (int nt = 0; nt < 13; nt++) {
                const int n0 = nt * 8;
                uint32_t b[2];
                b[0] = sm[SB + (n0 + g) * WS + kw + tg];
                b[1] = sm[SB + (n0 + g) * WS + kw + 4 + tg];
                mma_f16(acc[nt], a, b);
            }
        }

        const int row1 = i0 + r0 + g, row2 = row1 + 8;
        const float s1 = (row1 < NN) ? d_dis[row1] : 0.f;
        const float s2 = (row2 < NN) ? d_dis[row2] : 0.f;
        #pragma unroll
        for (int nt = 0; nt < 13; nt++) {
            const int c = nt * 8 + 2 * tg;
            if (c < C) {
                if (row1 < NN)
                    *(__half2*)&d_G16[(size_t)row1 * C + c] =
                        __floats2half2_rn(s1 * acc[nt][0], s1 * acc[nt][1]);
                if (row2 < NN)
                    *(__half2*)&d_G16[(size_t)row2 * C + c] =
                        __floats2half2_rn(s2 * acc[nt][2], s2 * acc[nt][3]);
            }
        }
        __syncthreads();
    }
}

// ---------------- gather + epilogues ----------------
__device__ __forceinline__ float4 ldg_h4(const __half* p) {
    uint2 r = *(const uint2*)p;
    __half2 a = *reinterpret_cast<__half2*>(&r.x);
    __half2 b = *reinterpret_cast<__half2*>(&r.y);
    float2 f0 = __half22float2(a), f1 = __half22float2(b);
    return make_float4(f0.x, f0.y, f1.x, f1.y);
}

__global__ void k_gather(int mode, const float* __restrict__ b1,
                         const float* __restrict__ bmu, const float* __restrict__ bls,
                         float* __restrict__ out) {
    int w = (blockIdx.x * blockDim.x + threadIdx.x) >> 5;
    int lane = threadIdx.x & 31;
    if (w >= NN || lane >= 25) return;
    int en = d_start[w];
    int n  = d_cnt[w];
    if (mode == 1 && lane == 0) d_cnt[w] = 0;   // reset for next run (post-read)
    int st = en - n;
    int p4 = lane * 4;

    float4 acc = ldg_h4(&d_G16[(size_t)w * C + p4]);   // self-loop term
    for (int j = 0; j < n; j++) {
        int s = d_csr[st + j];
        float4 v = ldg_h4(&d_G16[(size_t)s * C + p4]);
        acc.x += v.x; acc.y += v.y; acc.z += v.z; acc.w += v.w;
    }
    float sc = d_dis[w];

    if (mode == 0) {
        float4 bb = *(const float4*)&b1[p4];
        __half2 h0 = __floats2half2_rn(fmaxf(fmaf(sc, acc.x, bb.x), 0.f),
                                       fmaxf(fmaf(sc, acc.y, bb.y), 0.f));
        __half2 h1 = __floats2half2_rn(fmaxf(fmaf(sc, acc.z, bb.z), 0.f),
                                       fmaxf(fmaf(sc, acc.w, bb.w), 0.f));
        uint2 packed;
        packed.x = *reinterpret_cast<uint32_t*>(&h0);
        packed.y = *reinterpret_cast<uint32_t*>(&h1);
        *(uint2*)&d_H16[(size_t)w * C + p4] = packed;
    } else {
        float v[4] = { sc * acc.x, sc * acc.y, sc * acc.z, sc * acc.w };
        #pragma unroll
        for (int q = 0; q < 4; q++) {
            int c = p4 + q;
            if (c < OC) out[(size_t)w * OC + c]                          = v[q] + bmu[c];
            else        out[(size_t)NN * OC + (size_t)w * OC + (c - OC)] = v[q] + bls[c - OC];
        }
    }
}

extern "C" void kernel_launch(void* const* d_in, const int* in_sizes, int n_in,
                              void* d_out, int out_size) {
    const float* x   = (const float*)d_in[0];
    const int*   ei  = (const int*)  d_in[1];
    const float* W1  = (const float*)d_in[2];
    const float* b1  = (const float*)d_in[3];
    const float* Wmu = (const float*)d_in[4];
    const float* bmu = (const float*)d_in[5];
    const float* Wls = (const float*)d_in[6];
    const float* bls = (const float*)d_in[7];
    float* out = (float*)d_out;

    const int* src = ei;
    const int* dst = ei + NE;

    cudaFuncSetAttribute(k_gemm, cudaFuncAttributeMaxDynamicSharedMemorySize, SM_WORDS * 4);

    // CSR build (d_cnt arrives zeroed: load-time init or prior run's tail reset)
    k_deg<<<(NE + 255) / 256, 256>>>(dst);
    k_scan1<<<NBLK, 1024>>>();
    k_scan23<<<(NN + 255) / 256, 128>>>();
    k_fill<<<(NE + 255) / 256, 256>>>(src, dst);

    // layer 1
    k_gemm<<<GEMM_GRID, GEMM_THREADS, SM_WORDS * 4>>>(x, W1, nullptr, nullptr, 0);
    k_gather<<<(NN * 32 + 255) / 256, 256>>>(0, b1, nullptr, nullptr, nullptr);

    // layers 2+3 fused (mu | logstd column-concat)
    k_gemm<<<GEMM_GRID, GEMM_THREADS, SM_WORDS * 4>>>(nullptr, nullptr, Wmu, Wls, 1);
    k_gather<<<(NN * 32 + 255) / 256, 256>>>(1, nullptr, bmu, bls, out);
}